// round 11
// baseline (speedup 1.0000x reference)
#include <cuda_runtime.h>

// VoConstruction, algebraically reduced.  delta (U[:,2]) cancels.
//   d1 = 2*x1 ; d2 = 2*x2*(1-|x1|)
//   H00 = d1*c^2 + d2*s^2 ; H11 = d1*s^2 + d2*c^2  (real)
//   Re(H01) = Re(H10) = (d2-d1)*c*s*cos(2*psi) ; O swaps rows.
// Output per element: float4 (Re H10, Re H11, Re H00, Re H01)
//                   = (re, H11, H00, re)   [validated in R10: rel_err 1e-7]
//
// R10 ncu: DRAM 54%, issue 55%, fma/alu ~24% each -> latency/issue limited by
// accurate sincos expansion + low per-thread MLP. This version: MUFU fast
// intrinsics (3 MUFU/element) + 4 elements/thread with 5 front-batched
// LDG.128 and 4 STG.128.

__global__ void __launch_bounds__(256)
vo_kernel(const float4* __restrict__ U4,
          const float4* __restrict__ x1_4,
          const float4* __restrict__ x2_4,
          float4* __restrict__ out4,
          int nquads)
{
    int t = blockIdx.x * blockDim.x + threadIdx.x;
    if (t >= nquads) return;

    // Front-batched loads: 3 float4 of U + x1 + x2  (MLP = 5)
    float4 ua  = U4[3 * t + 0];
    float4 ub  = U4[3 * t + 1];
    float4 uc  = U4[3 * t + 2];
    float4 l1v = x1_4[t];
    float4 l2v = x2_4[t];

    float psi[4]   = { ua.x, ua.w, ub.z, uc.y };
    float theta[4] = { ua.y, ub.x, ub.w, uc.z };
    float lam1[4]  = { l1v.x, l1v.y, l1v.z, l1v.w };
    float xv2[4]   = { l2v.x, l2v.y, l2v.z, l2v.w };

    float4 res[4];

    #pragma unroll
    for (int e = 0; e < 4; e++) {
        float d1 = 2.0f * lam1[e];
        float d2 = 2.0f * xv2[e] * (1.0f - fabsf(lam1[e]));

        float s, c;
        __sincosf(theta[e], &s, &c);          // 2x MUFU
        float c2 = c * c, s2 = s * s, cs = c * s;

        float H00 = d1 * c2 + d2 * s2;
        float H11 = d1 * s2 + d2 * c2;

        float re = (d2 - d1) * cs * __cosf(2.0f * psi[e]);   // 1x MUFU

        res[e] = make_float4(re, H11, H00, re);
    }

    #pragma unroll
    for (int e = 0; e < 4; e++)
        out4[4 * t + e] = res[e];
}

extern "C" void kernel_launch(void* const* d_in, const int* in_sizes, int n_in,
                              void* d_out, int out_size)
{
    // in_sizes are element counts: U [B,3] is the largest input (3B),
    // x1/x2 are the two B-sized inputs in original order, O is tiny (folded in).
    long smax = 0;
    int iU = 0;
    for (int i = 0; i < n_in; i++)
        if ((long)in_sizes[i] > smax) { smax = in_sizes[i]; iU = i; }

    long B = smax / 3;
    long B_cap = (long)out_size / 4;          // out_size = 4*B floats
    if (B_cap > 0 && B_cap < B) B = B_cap;

    int ix1 = -1, ix2 = -1;
    for (int i = 0; i < n_in; i++) {
        if (i == iU) continue;
        if ((long)in_sizes[i] >= B) {
            if (ix1 < 0) ix1 = i;
            else if (ix2 < 0) ix2 = i;
        }
    }
    if (ix1 < 0) ix1 = (iU == 0) ? 1 : 0;
    if (ix2 < 0) { ix2 = 0; while ((ix2 == iU || ix2 == ix1) && ix2 < n_in - 1) ix2++; }

    const float4* U4   = (const float4*)d_in[iU];
    const float4* x1_4 = (const float4*)d_in[ix1];
    const float4* x2_4 = (const float4*)d_in[ix2];
    float4* out4 = (float4*)d_out;

    int nquads = (int)(B / 4);                // B = 4194304, divisible by 4
    int threads = 256;
    int blocks = (nquads + threads - 1) / threads;
    vo_kernel<<<blocks, threads>>>(U4, x1_4, x2_4, out4, nquads);
}

// round 12
// speedup vs baseline: 1.0901x; 1.0901x over previous
#include <cuda_runtime.h>

// VoConstruction, algebraically reduced.  delta (U[:,2]) cancels.
//   d1 = 2*x1 ; d2 = 2*x2*(1-|x1|)
//   H00 = d1*c^2 + d2*s^2 ; H11 = d1*s^2 + d2*c^2  (real)
//   Re(H01) = Re(H10) = (d2-d1)*c*s*cos(2*psi) ; O swaps rows.
// Output per element: float4 (re, H11, H00, re)  [validated R10/R11, rel_err ~1e-7]
//
// R10 (1 elem/thread, accurate sincos): 25.2us, DRAM 54%, issue 55%.
// R11 (4 elem/thread, fast math):       27.6us, DRAM 46%, issue 14% — vector
//   restructure regressed (thread-count latency hiding beats per-thread MLP).
// This round: R10 shape + R11 fast math. 4M threads, scalar coalesced loads,
// one STG.128 per thread, 3 MUFU ops of compute.

__global__ void __launch_bounds__(256)
vo_kernel(const float* __restrict__ U,
          const float* __restrict__ x1,
          const float* __restrict__ x2,
          float4* __restrict__ out4,
          int B)
{
    int b = blockIdx.x * blockDim.x + threadIdx.x;
    if (b >= B) return;

    float psi   = U[3 * b + 0];
    float theta = U[3 * b + 1];
    float lam1  = x1[b];
    float xv2   = x2[b];

    float d1 = 2.0f * lam1;
    float d2 = 2.0f * xv2 * (1.0f - fabsf(lam1));

    float s, c;
    __sincosf(theta, &s, &c);                    // 2x MUFU
    float c2 = c * c, s2 = s * s, cs = c * s;

    float H00 = d1 * c2 + d2 * s2;
    float H11 = d1 * s2 + d2 * c2;

    float re = (d2 - d1) * cs * __cosf(2.0f * psi);   // 1x MUFU

    out4[b] = make_float4(re, H11, H00, re);
}

extern "C" void kernel_launch(void* const* d_in, const int* in_sizes, int n_in,
                              void* d_out, int out_size)
{
    // in_sizes are element counts: U [B,3] is the largest input (3B),
    // x1/x2 are the two B-sized inputs in original order, O is tiny (folded in).
    long smax = 0;
    int iU = 0;
    for (int i = 0; i < n_in; i++)
        if ((long)in_sizes[i] > smax) { smax = in_sizes[i]; iU = i; }

    long B = smax / 3;
    long B_cap = (long)out_size / 4;          // out_size = 4*B floats
    if (B_cap > 0 && B_cap < B) B = B_cap;

    int ix1 = -1, ix2 = -1;
    for (int i = 0; i < n_in; i++) {
        if (i == iU) continue;
        if ((long)in_sizes[i] >= B) {
            if (ix1 < 0) ix1 = i;
            else if (ix2 < 0) ix2 = i;
        }
    }
    if (ix1 < 0) ix1 = (iU == 0) ? 1 : 0;
    if (ix2 < 0) { ix2 = 0; while ((ix2 == iU || ix2 == ix1) && ix2 < n_in - 1) ix2++; }

    const float* U  = (const float*)d_in[iU];
    const float* x1 = (const float*)d_in[ix1];
    const float* x2 = (const float*)d_in[ix2];
    float4* out4 = (float4*)d_out;

    int Bi = (int)B;
    int threads = 256;
    int blocks = (Bi + threads - 1) / threads;
    vo_kernel<<<blocks, threads>>>(U, x1, x2, out4, Bi);
}

// round 13
// speedup vs baseline: 1.1502x; 1.0552x over previous
#include <cuda_runtime.h>

// VoConstruction, algebraically reduced.  delta (U[:,2]) cancels.
//   d1 = 2*x1 ; d2 = 2*x2*(1-|x1|)
//   H00 = d1*c^2 + d2*s^2 ; H11 = d1*s^2 + d2*c^2  (real)
//   Re(H01) = Re(H10) = (d2-d1)*c*s*cos(2*psi) ; O swaps rows.
// Output per element: float4 (re, H11, H00, re)  [validated, rel_err ~2.5e-7]
//
// Tuning history (ncu kernel time):
//   R10 1 elem/thread + accurate sincos : 25.2us  (DRAM 54%, issue 55%)
//   R11 4 elem/thread + fast math       : 27.6us  (DRAM 46% — regression)
//   R12 1 elem/thread + fast math       : 23.7us  (DRAM 59%, issue 27%)  <- base
// This round: add streaming cache hints (__ldcs/__stcs). The 151MB stream is
// ~1.2x L2 capacity; evict-first policy stops the read and write streams from
// thrashing each other. Shape/math unchanged.

__global__ void __launch_bounds__(256)
vo_kernel(const float* __restrict__ U,
          const float* __restrict__ x1,
          const float* __restrict__ x2,
          float4* __restrict__ out4,
          int B)
{
    int b = blockIdx.x * blockDim.x + threadIdx.x;
    if (b >= B) return;

    float psi   = __ldcs(&U[3 * b + 0]);
    float theta = __ldcs(&U[3 * b + 1]);
    float lam1  = __ldcs(&x1[b]);
    float xv2   = __ldcs(&x2[b]);

    float d1 = 2.0f * lam1;
    float d2 = 2.0f * xv2 * (1.0f - fabsf(lam1));

    float s, c;
    __sincosf(theta, &s, &c);                         // 2x MUFU
    float c2 = c * c, s2 = s * s, cs = c * s;

    float H00 = d1 * c2 + d2 * s2;
    float H11 = d1 * s2 + d2 * c2;

    float re = (d2 - d1) * cs * __cosf(2.0f * psi);   // 1x MUFU

    __stcs(&out4[b], make_float4(re, H11, H00, re));
}

extern "C" void kernel_launch(void* const* d_in, const int* in_sizes, int n_in,
                              void* d_out, int out_size)
{
    // in_sizes are element counts: U [B,3] is the largest input (3B),
    // x1/x2 are the two B-sized inputs in original order, O is tiny (folded in).
    long smax = 0;
    int iU = 0;
    for (int i = 0; i < n_in; i++)
        if ((long)in_sizes[i] > smax) { smax = in_sizes[i]; iU = i; }

    long B = smax / 3;
    long B_cap = (long)out_size / 4;          // out_size = 4*B floats
    if (B_cap > 0 && B_cap < B) B = B_cap;

    int ix1 = -1, ix2 = -1;
    for (int i = 0; i < n_in; i++) {
        if (i == iU) continue;
        if ((long)in_sizes[i] >= B) {
            if (ix1 < 0) ix1 = i;
            else if (ix2 < 0) ix2 = i;
        }
    }
    if (ix1 < 0) ix1 = (iU == 0) ? 1 : 0;
    if (ix2 < 0) { ix2 = 0; while ((ix2 == iU || ix2 == ix1) && ix2 < n_in - 1) ix2++; }

    const float* U  = (const float*)d_in[iU];
    const float* x1 = (const float*)d_in[ix1];
    const float* x2 = (const float*)d_in[ix2];
    float4* out4 = (float4*)d_out;

    int Bi = (int)B;
    int threads = 256;
    int blocks = (Bi + threads - 1) / threads;
    vo_kernel<<<blocks, threads>>>(U, x1, x2, out4, Bi);
}